// round 3
// baseline (speedup 1.0000x reference)
#include <cuda_runtime.h>

#define HH 32
#define WW 32
#define BB 16
#define NPOS 512
#define PIX 8              // pixels per block (row-contiguous)
#define THREADS 1024
#define GRID 128
#define NLAYERS 4
#define AROW 68            // floats per A-octant (64 data + 4 pad)
#define SROW 548           // floats per pixel row (8*68=544 + 4 pad)
#define LHW (NPOS * HH * WW)

// State scratch (3 buffers — each address written once per launch) + barrier counters.
__device__ float g_state[3][BB * HH * WW];
__device__ unsigned g_bar[NLAYERS];   // monotonically increasing across graph replays

__device__ __forceinline__ float sigmoidf(float x) {
    return __fdividef(1.0f, 1.0f + __expf(-x));
}

// Replay-safe grid barrier: counters never reset; epoch derived from ticket.
__device__ __forceinline__ void grid_barrier(int b) {
    __threadfence();
    __syncthreads();
    if (threadIdx.x == 0) {
        unsigned ticket = atomicAdd(&g_bar[b], 1u);
        unsigned target = (ticket / GRID + 1u) * GRID;
        while (*((volatile unsigned*)&g_bar[b]) < target) { }
        __threadfence();
    }
    __syncthreads();
}

__global__ __launch_bounds__(THREADS, 1)
void asic_fused(const float* __restrict__ x,    // (B,H,W) input state
                const float* __restrict__ tg,   // (L,NPOS,H,W) raw gates
                float* __restrict__ out)        // (B,H,W)
{
    __shared__ __align__(16) float s_s[PIX * SROW];

    const int tid = threadIdx.x;
    const int pixBase = blockIdx.x * PIX;

    // ---- fixed thread mapping: 8 threads per (pixel,batch) pair ----
    const int oct    = tid & 7;           // A-octant = top 3 bits of combo j
    const int pairId = tid >> 3;
    const int batch  = pairId & (BB - 1);
    const int pixL   = pairId >> 4;       // 0..7
    const int pixel  = pixBase + pixL;
    const int h = pixel >> 5;
    const int w = pixel & 31;

    // precompute the 9 wrapped window offsets (h+{0,1,2}, w+{-1,0,1})
    int offs[9];
#pragma unroll
    for (int i0 = 0; i0 < 3; i0++) {
        int hh = h + i0; if (hh >= HH) hh -= HH;
#pragma unroll
        for (int i1 = 0; i1 < 3; i1++) {
            int ww2 = w + i1 - 1;
            if (ww2 < 0) ww2 += WW;
            if (ww2 >= WW) ww2 -= WW;
            offs[i0 * 3 + i1] = batch * (HH * WW) + hh * WW + ww2;
        }
    }

    // ---- prefetch layer-0 raw gates into registers ----
    float rg[4];
#pragma unroll
    for (int it = 0; it < 4; it++) {
        int idx = tid + it * THREADS;
        int p = idx >> 3, i = idx & 7;
        rg[it] = __ldg(tg + p * (HH * WW) + pixBase + i);
    }

#pragma unroll
    for (int L = 0; L < NLAYERS; L++) {
        // ---- stage sigmoid(gates) into smem (conflict-free skewed layout) ----
#pragma unroll
        for (int it = 0; it < 4; it++) {
            int idx = tid + it * THREADS;
            int p = idx >> 3, i = idx & 7;
            s_s[i * SROW + (p >> 6) * AROW + (p & 63)] = sigmoidf(rg[it]);
        }
        __syncthreads();

        // ---- prefetch NEXT layer's raw gates (overlaps with compute below) ----
        if (L < NLAYERS - 1) {
            const float* tn = tg + (L + 1) * LHW;
#pragma unroll
            for (int it = 0; it < 4; it++) {
                int idx = tid + it * THREADS;
                int p = idx >> 3, i = idx & 7;
                rg[it] = __ldg(tn + p * (HH * WW) + pixBase + i);
            }
        }

        // ---- gather 3x3 wrapped window (L2-coherent loads for peer-written state) ----
        const float* src = (L == 0) ? x : g_state[L - 1];
        float v[9];
#pragma unroll
        for (int k = 0; k < 9; k++) v[k] = __ldcg(src + offs[k]);

        // ---- partial products: A=j>>6 (fixed=oct), B=(j>>3)&7, C=j&7 ----
        float PB[8], PC[8];
#pragma unroll
        for (int q = 0; q < 8; q++) {
            PB[q] = ((q & 4) ? v[3] : 1.0f - v[3])
                  * ((q & 2) ? v[4] : 1.0f - v[4])
                  * ((q & 1) ? v[5] : 1.0f - v[5]);
            PC[q] = ((q & 4) ? v[6] : 1.0f - v[6])
                  * ((q & 2) ? v[7] : 1.0f - v[7])
                  * ((q & 1) ? v[8] : 1.0f - v[8]);
        }
        const float PA = ((oct & 4) ? v[0] : 1.0f - v[0])
                       * ((oct & 2) ? v[1] : 1.0f - v[1])
                       * ((oct & 1) ? v[2] : 1.0f - v[2]);

        // ---- contraction over this thread's 64 combos (LDS.128, conflict-free) ----
        const float* sp = s_s + pixL * SROW + oct * AROW;
        float acc0 = 0.0f, acc1 = 0.0f;
#pragma unroll
        for (int q = 0; q < 8; q += 2) {
            float4 a0 = *(const float4*)(sp + q * 8);
            float4 a1 = *(const float4*)(sp + q * 8 + 4);
            float4 b0 = *(const float4*)(sp + q * 8 + 8);
            float4 b1 = *(const float4*)(sp + q * 8 + 12);
            float innerA = ((PC[0] * a0.x + PC[1] * a0.y) + (PC[2] * a0.z + PC[3] * a0.w))
                         + ((PC[4] * a1.x + PC[5] * a1.y) + (PC[6] * a1.z + PC[7] * a1.w));
            float innerB = ((PC[0] * b0.x + PC[1] * b0.y) + (PC[2] * b0.z + PC[3] * b0.w))
                         + ((PC[4] * b1.x + PC[5] * b1.y) + (PC[6] * b1.z + PC[7] * b1.w));
            acc0 = fmaf(PB[q], innerA, acc0);
            acc1 = fmaf(PB[q + 1], innerB, acc1);
        }
        float acc = PA * (acc0 + acc1);

        // reduce over the 8 A-octant lanes
        acc += __shfl_xor_sync(0xffffffffu, acc, 1);
        acc += __shfl_xor_sync(0xffffffffu, acc, 2);
        acc += __shfl_xor_sync(0xffffffffu, acc, 4);

        if (oct == 0) {
            float* dst = (L == NLAYERS - 1) ? out : g_state[L];
            dst[batch * (HH * WW) + pixel] = fminf(fmaxf(acc, 0.0f), 1.0f);
        }

        // ---- grid-wide handoff (also guards smem staging overwrite next layer) ----
        if (L < NLAYERS - 1) grid_barrier(L);
    }
}

extern "C" void kernel_launch(void* const* d_in, const int* in_sizes, int n_in,
                              void* d_out, int out_size) {
    // Identify inputs by size (x: 16384, tg: 2097152)
    const float* x  = (const float*)d_in[0];
    const float* tg = (const float*)d_in[1];
    if (n_in >= 2 && in_sizes[0] > in_sizes[1]) {
        x  = (const float*)d_in[1];
        tg = (const float*)d_in[0];
    }
    float* out = (float*)d_out;

    asic_fused<<<GRID, THREADS>>>(x, tg, out);
}

// round 4
// speedup vs baseline: 1.0122x; 1.0122x over previous
#include <cuda_runtime.h>

#define HH 32
#define WW 32
#define BB 16
#define NPOS 512
#define PIX 8              // pixels per block (row-contiguous quarter-row)
#define THREADS 1024
#define GRID 128
#define NLAYERS 4
#define AROW 68            // floats per A-octant (64 data + 4 pad)
#define SROW 548           // floats per pixel row (8*68=544 + 4 pad)
#define LHW (NPOS * HH * WW)

// State scratch (3 buffers, each address written once per launch).
__device__ float g_state[3][BB * HH * WW];
// Replay-safe sync state: monotonic, never reset.
__device__ unsigned g_epoch[GRID];
__device__ unsigned g_flag[NLAYERS][GRID];

__device__ __forceinline__ float sigmoidf(float x) {
    return __fdividef(1.0f, 1.0f + __expf(-x));
}

__global__ __launch_bounds__(THREADS, 1)
void asic_fused(const float* __restrict__ x,    // (B,H,W) input state
                const float* __restrict__ tg,   // (L,NPOS,H,W) raw gates
                float* __restrict__ out)        // (B,H,W)
{
    __shared__ __align__(16) float s_s[2][PIX * SROW];
    __shared__ unsigned s_epoch;

    const int tid = threadIdx.x;
    const int bid = blockIdx.x;
    const int pixBase = bid * PIX;

    // Per-block monotonic epoch (one bump per launch -> replay-safe flags).
    if (tid == 0) s_epoch = atomicAdd(&g_epoch[bid], 1u) + 1u;

    // ---- fixed thread mapping: 8 threads per (pixel,batch) pair ----
    const int oct    = tid & 7;           // A-octant = top 3 bits of combo j
    const int pairId = tid >> 3;
    const int batch  = pairId & (BB - 1);
    const int pixL   = pairId >> 4;       // 0..7
    const int pixel  = pixBase + pixL;
    const int h = pixel >> 5;
    const int w = pixel & 31;

    // My 9 producer-neighbor block ids (rows r..r+2, col-quarters q-1..q+1, wrapped).
    int nbrId = 0;
    if (tid < 9) {
        int r = bid >> 2, q = bid & 3;
        int rr = (r + tid / 3) & 31;
        int qq = (q + (tid % 3) - 1) & 3;
        nbrId = rr * 4 + qq;
    }

    // precompute the 9 wrapped window offsets (h+{0,1,2}, w+{-1,0,1})
    int offs[9];
#pragma unroll
    for (int i0 = 0; i0 < 3; i0++) {
        int hh = h + i0; if (hh >= HH) hh -= HH;
#pragma unroll
        for (int i1 = 0; i1 < 3; i1++) {
            int ww2 = w + i1 - 1;
            if (ww2 < 0) ww2 += WW;
            if (ww2 >= WW) ww2 -= WW;
            offs[i0 * 3 + i1] = batch * (HH * WW) + hh * WW + ww2;
        }
    }

    // ---- prologue: stage layer-0 gates, prefetch layer-1, load x window ----
    float rg[4];
#pragma unroll
    for (int it = 0; it < 4; it++) {
        int idx = tid + it * THREADS;
        int p = idx >> 3, i = idx & 7;
        rg[it] = __ldg(tg + p * (HH * WW) + pixBase + i);
    }
#pragma unroll
    for (int it = 0; it < 4; it++) {
        int idx = tid + it * THREADS;
        int p = idx >> 3, i = idx & 7;
        s_s[0][i * SROW + (p >> 6) * AROW + (p & 63)] = sigmoidf(rg[it]);
    }
#pragma unroll
    for (int it = 0; it < 4; it++) {
        int idx = tid + it * THREADS;
        int p = idx >> 3, i = idx & 7;
        rg[it] = __ldg(tg + LHW + p * (HH * WW) + pixBase + i);
    }
    float v[9];
#pragma unroll
    for (int k = 0; k < 9; k++) v[k] = __ldg(x + offs[k]);

    __syncthreads();                 // s_s[0] + s_epoch visible
    const unsigned target = s_epoch;

#pragma unroll
    for (int L = 0; L < NLAYERS; L++) {
        // ---- partial products: A=j>>6 (fixed=oct), B=(j>>3)&7, C=j&7 ----
        float PB[8], PC[8];
#pragma unroll
        for (int q = 0; q < 8; q++) {
            PB[q] = ((q & 4) ? v[3] : 1.0f - v[3])
                  * ((q & 2) ? v[4] : 1.0f - v[4])
                  * ((q & 1) ? v[5] : 1.0f - v[5]);
            PC[q] = ((q & 4) ? v[6] : 1.0f - v[6])
                  * ((q & 2) ? v[7] : 1.0f - v[7])
                  * ((q & 1) ? v[8] : 1.0f - v[8]);
        }
        const float PA = ((oct & 4) ? v[0] : 1.0f - v[0])
                       * ((oct & 2) ? v[1] : 1.0f - v[1])
                       * ((oct & 1) ? v[2] : 1.0f - v[2]);

        // ---- contraction over this thread's 64 combos (LDS.128, conflict-free) ----
        const float* sp = s_s[L & 1] + pixL * SROW + oct * AROW;
        float acc0 = 0.0f, acc1 = 0.0f;
#pragma unroll
        for (int q = 0; q < 8; q += 2) {
            float4 a0 = *(const float4*)(sp + q * 8);
            float4 a1 = *(const float4*)(sp + q * 8 + 4);
            float4 b0 = *(const float4*)(sp + q * 8 + 8);
            float4 b1 = *(const float4*)(sp + q * 8 + 12);
            float innerA = ((PC[0] * a0.x + PC[1] * a0.y) + (PC[2] * a0.z + PC[3] * a0.w))
                         + ((PC[4] * a1.x + PC[5] * a1.y) + (PC[6] * a1.z + PC[7] * a1.w));
            float innerB = ((PC[0] * b0.x + PC[1] * b0.y) + (PC[2] * b0.z + PC[3] * b0.w))
                         + ((PC[4] * b1.x + PC[5] * b1.y) + (PC[6] * b1.z + PC[7] * b1.w));
            acc0 = fmaf(PB[q], innerA, acc0);
            acc1 = fmaf(PB[q + 1], innerB, acc1);
        }
        float acc = PA * (acc0 + acc1);

        acc += __shfl_xor_sync(0xffffffffu, acc, 1);
        acc += __shfl_xor_sync(0xffffffffu, acc, 2);
        acc += __shfl_xor_sync(0xffffffffu, acc, 4);

        if (oct == 0) {
            float* dst = (L == NLAYERS - 1) ? out : g_state[L];
            dst[batch * (HH * WW) + pixel] = fminf(fmaxf(acc, 0.0f), 1.0f);
        }

        if (L < NLAYERS - 1) {
            // ---- publish: my block's layer-L outputs are done ----
            __threadfence();
            __syncthreads();
            if (tid == 0) atomicExch(&g_flag[L][bid], target);

            // ---- useful work while neighbors finish: stage next gates ----
#pragma unroll
            for (int it = 0; it < 4; it++) {
                int idx = tid + it * THREADS;
                int p = idx >> 3, i = idx & 7;
                s_s[(L + 1) & 1][i * SROW + (p >> 6) * AROW + (p & 63)] = sigmoidf(rg[it]);
            }
            if (L < NLAYERS - 2) {
                const float* tn = tg + (L + 2) * LHW;
#pragma unroll
                for (int it = 0; it < 4; it++) {
                    int idx = tid + it * THREADS;
                    int p = idx >> 3, i = idx & 7;
                    rg[it] = __ldg(tn + p * (HH * WW) + pixBase + i);
                }
            }

            // ---- wait only on my 9 producer neighbors ----
            if (tid < 9) {
                while (*((volatile unsigned*)&g_flag[L][nbrId]) < target) { }
                __threadfence();
            }
            __syncthreads();         // flags seen + s_s[(L+1)&1] staged

            // ---- reload window from the freshly written state (L2-coherent) ----
            const float* src = g_state[L];
#pragma unroll
            for (int k = 0; k < 9; k++) v[k] = __ldcg(src + offs[k]);
        }
    }
}

extern "C" void kernel_launch(void* const* d_in, const int* in_sizes, int n_in,
                              void* d_out, int out_size) {
    // Identify inputs by size (x: 16384, tg: 2097152)
    const float* x  = (const float*)d_in[0];
    const float* tg = (const float*)d_in[1];
    if (n_in >= 2 && in_sizes[0] > in_sizes[1]) {
        x  = (const float*)d_in[1];
        tg = (const float*)d_in[0];
    }
    float* out = (float*)d_out;

    asic_fused<<<GRID, THREADS>>>(x, tg, out);
}

// round 5
// speedup vs baseline: 1.2393x; 1.2243x over previous
#include <cuda_runtime.h>

#define HH 32
#define WW 32
#define BB 16
#define NPOS 512
#define PIX 8              // pixels per block (row-contiguous quarter-row)
#define THREADS 512
#define GRID 128
#define AROW 68            // floats per A-octant (64 data + 4 pad)
#define SROW 548           // floats per pixel row (8*68=544 + 4 pad)
#define LHW (NPOS * HH * WW)

// Ping-pong state scratch (no device allocation allowed).
__device__ float g_state[2][BB * HH * WW];

__device__ __forceinline__ float sigmoidf(float x) {
    return __fdividef(1.0f, 1.0f + __expf(-x));
}

// Build the 8 products for one bit-triple (v0 = MSB of the triple index).
__device__ __forceinline__ void triple8(float v0, float v1, float v2, float* P) {
    float c0 = 1.0f - v0, c1 = 1.0f - v1, c2 = 1.0f - v2;
    float t0 = c1 * c2, t1 = c1 * v2, t2 = v1 * c2, t3 = v1 * v2;
    P[0] = c0 * t0; P[1] = c0 * t1; P[2] = c0 * t2; P[3] = c0 * t3;
    P[4] = v0 * t0; P[5] = v0 * t1; P[6] = v0 * t2; P[7] = v0 * t3;
}

__global__ __launch_bounds__(THREADS, 1)
void asic_layer(const float* __restrict__ src,   // (B,H,W) previous state
                const float* __restrict__ tg,    // (NPOS,H,W) this layer's gates
                float* __restrict__ dst)         // (B,H,W)
{
    __shared__ __align__(16) float s_s[PIX * SROW];

    const int tid = threadIdx.x;
    const int pixBase = blockIdx.x * PIX;

    // ---- stage + sigmoid the 8 pixels' LUT gates (LDG.128 granularity) ----
    // 1024 float4 chunks: chunk c -> p = c>>1, ih = (c&1)*4  (pixels ih..ih+3)
#pragma unroll
    for (int it = 0; it < 2; it++) {
        int c = tid + it * THREADS;
        int p = c >> 1;
        int ih = (c & 1) * 4;
        float4 g = *(const float4*)(tg + p * (HH * WW) + pixBase + ih);
        int base = (p >> 6) * AROW + (p & 63);
        s_s[(ih + 0) * SROW + base] = sigmoidf(g.x);
        s_s[(ih + 1) * SROW + base] = sigmoidf(g.y);
        s_s[(ih + 2) * SROW + base] = sigmoidf(g.z);
        s_s[(ih + 3) * SROW + base] = sigmoidf(g.w);
    }
    __syncthreads();

    // ---- thread mapping: (pixel, batch-pair, A-octant) ----
    const int oct  = tid & 7;            // A = top 3 bits of combo j
    const int bp   = (tid >> 3) & 7;     // batches bp and bp+8
    const int pixL = tid >> 6;           // 0..7
    const int pixel = pixBase + pixL;
    const int h = pixel >> 5;
    const int w = pixel & 31;
    const int b0 = bp, b1 = bp + 8;

    // ---- gather 3x3 wrapped windows for both batches ----
    float v0[9], v1[9];
#pragma unroll
    for (int i0 = 0; i0 < 3; i0++) {
        int hh = h + i0; if (hh >= HH) hh -= HH;
#pragma unroll
        for (int i1 = 0; i1 < 3; i1++) {
            int ww2 = w + i1 - 1;
            if (ww2 < 0) ww2 += WW;
            if (ww2 >= WW) ww2 -= WW;
            int spat = hh * WW + ww2;
            v0[i0 * 3 + i1] = __ldg(src + b0 * (HH * WW) + spat);
            v1[i0 * 3 + i1] = __ldg(src + b1 * (HH * WW) + spat);
        }
    }

    // ---- partial products: A=j>>6 (fixed=oct), B=(j>>3)&7, C=j&7 ----
    float PB0[8], PC0[8], PB1[8], PC1[8];
    triple8(v0[3], v0[4], v0[5], PB0);
    triple8(v0[6], v0[7], v0[8], PC0);
    triple8(v1[3], v1[4], v1[5], PB1);
    triple8(v1[6], v1[7], v1[8], PC1);
    const float PA0 = ((oct & 4) ? v0[0] : 1.0f - v0[0])
                    * ((oct & 2) ? v0[1] : 1.0f - v0[1])
                    * ((oct & 1) ? v0[2] : 1.0f - v0[2]);
    const float PA1 = ((oct & 4) ? v1[0] : 1.0f - v1[0])
                    * ((oct & 2) ? v1[1] : 1.0f - v1[1])
                    * ((oct & 1) ? v1[2] : 1.0f - v1[2]);

    // ---- contraction: 64 combos, each gate read feeds BOTH batches ----
    const float* sp = s_s + pixL * SROW + oct * AROW;
    float acc0a = 0.0f, acc0b = 0.0f, acc1a = 0.0f, acc1b = 0.0f;
#pragma unroll
    for (int q = 0; q < 8; q += 2) {
        float4 r0 = *(const float4*)(sp + q * 8);
        float4 r1 = *(const float4*)(sp + q * 8 + 4);
        float4 r2 = *(const float4*)(sp + q * 8 + 8);
        float4 r3 = *(const float4*)(sp + q * 8 + 12);

        float iA0 = ((PC0[0] * r0.x + PC0[1] * r0.y) + (PC0[2] * r0.z + PC0[3] * r0.w))
                  + ((PC0[4] * r1.x + PC0[5] * r1.y) + (PC0[6] * r1.z + PC0[7] * r1.w));
        float iA1 = ((PC1[0] * r0.x + PC1[1] * r0.y) + (PC1[2] * r0.z + PC1[3] * r0.w))
                  + ((PC1[4] * r1.x + PC1[5] * r1.y) + (PC1[6] * r1.z + PC1[7] * r1.w));
        float iB0 = ((PC0[0] * r2.x + PC0[1] * r2.y) + (PC0[2] * r2.z + PC0[3] * r2.w))
                  + ((PC0[4] * r3.x + PC0[5] * r3.y) + (PC0[6] * r3.z + PC0[7] * r3.w));
        float iB1 = ((PC1[0] * r2.x + PC1[1] * r2.y) + (PC1[2] * r2.z + PC1[3] * r2.w))
                  + ((PC1[4] * r3.x + PC1[5] * r3.y) + (PC1[6] * r3.z + PC1[7] * r3.w));

        acc0a = fmaf(PB0[q], iA0, acc0a);
        acc1a = fmaf(PB1[q], iA1, acc1a);
        acc0b = fmaf(PB0[q + 1], iB0, acc0b);
        acc1b = fmaf(PB1[q + 1], iB1, acc1b);
    }
    float acc0 = PA0 * (acc0a + acc0b);
    float acc1 = PA1 * (acc1a + acc1b);

    // reduce over the 8 A-octant lanes (oct = tid bits 0..2)
#pragma unroll
    for (int d = 1; d <= 4; d <<= 1) {
        acc0 += __shfl_xor_sync(0xffffffffu, acc0, d);
        acc1 += __shfl_xor_sync(0xffffffffu, acc1, d);
    }

    if (oct == 0) {
        dst[b0 * (HH * WW) + pixel] = fminf(fmaxf(acc0, 0.0f), 1.0f);
        dst[b1 * (HH * WW) + pixel] = fminf(fmaxf(acc1, 0.0f), 1.0f);
    }
}

extern "C" void kernel_launch(void* const* d_in, const int* in_sizes, int n_in,
                              void* d_out, int out_size) {
    // Identify inputs by size (x: 16384, tg: 2097152)
    const float* x  = (const float*)d_in[0];
    const float* tg = (const float*)d_in[1];
    if (n_in >= 2 && in_sizes[0] > in_sizes[1]) {
        x  = (const float*)d_in[1];
        tg = (const float*)d_in[0];
    }
    float* out = (float*)d_out;

    float* st;
    cudaGetSymbolAddress((void**)&st, g_state);
    float* s0 = st;
    float* s1 = st + BB * HH * WW;

    asic_layer<<<GRID, THREADS>>>(x,  tg + 0 * LHW, s0);
    asic_layer<<<GRID, THREADS>>>(s0, tg + 1 * LHW, s1);
    asic_layer<<<GRID, THREADS>>>(s1, tg + 2 * LHW, s0);
    asic_layer<<<GRID, THREADS>>>(s0, tg + 3 * LHW, out);
}